// round 1
// baseline (speedup 1.0000x reference)
#include <cuda_runtime.h>

#define N_IMG 8
#define H 32
#define W 32
#define CIN 32
#define COUT 64
#define HO 30
#define WO 30
#define NPIX (N_IMG*HO*WO)       // 7200
#define CHUNK_PX 16
#define NCHUNKS (NPIX/CHUNK_PX)  // 450 (exact)
#define PDIM (3*3*CIN)           // 288

// Scratch (device globals: no allocation allowed in kernel_launch)
__device__ float g_v1[N_IMG*CIN*H*W];   // max(x,0.1), NCHW
__device__ float g_v2[N_IMG*CIN*H*W];   // max(-x,0.1), NCHW
__device__ float g_ek1[PDIM*COUT];      // exp(k1), [p][cout]
__device__ float g_ek2[PDIM*COUT];      // exp(k2), [p][cout]
__device__ int   g_ticket;

// ---------------------------------------------------------------------------
// Prep 1: clamp + NHWC -> NCHW transpose (coalesced read AND write via smem)
// ---------------------------------------------------------------------------
__global__ void prep_vals(const float* __restrict__ x) {
    __shared__ float tile[32][33];
    const int n = blockIdx.x >> 5;
    const int h = blockIdx.x & 31;
    {
        const int c = threadIdx.x;      // contiguous in gmem -> coalesced read
        const int w = threadIdx.y;
        tile[w][c] = x[(((n*H + h)*W + w)*CIN) + c];
    }
    __syncthreads();
    {
        const int w = threadIdx.x;      // contiguous in output -> coalesced write
        const int c = threadIdx.y;
        const float v = tile[w][c];
        const int o = ((n*CIN + c)*H + h)*W + w;
        g_v1[o] = fmaxf(v, 0.1f);
        g_v2[o] = fmaxf(-v, 0.1f);
    }
}

// ---------------------------------------------------------------------------
// Prep 2: exp(weights) + ticket reset
// ---------------------------------------------------------------------------
__global__ void prep_w(const float* __restrict__ k1, const float* __restrict__ k2) {
    const int i = blockIdx.x * 256 + threadIdx.x;
    if (i == 0) g_ticket = 0;
    if (i < PDIM*COUT) {
        g_ek1[i] = expf(k1[i]);
        g_ek2[i] = expf(k2[i]);
    }
}

// ---------------------------------------------------------------------------
// Main: dynamic-ticket chunks of 16 pixels x 64 couts.
// 128 threads = 16 pixel-lanes x 8 cout-groups (8 couts each).
// Per p: 2 scalar v LDGs (coalesced) + 4 LDG.128 weights (warp-broadcast,
// L1-resident) + 32 FMUL + 32 FMNMX (dual fma/alu pipe mix).
// ---------------------------------------------------------------------------
__global__ void __launch_bounds__(128, 4)
morph_main(const float* __restrict__ bias, float* __restrict__ out) {
    __shared__ int s_chunk;
    const int t  = threadIdx.x;
    const int px = t & 15;        // pixel lane within chunk
    const int cg = t >> 4;        // cout group 0..7
    const int c0 = cg * 8;

    for (;;) {
        if (t == 0) s_chunk = atomicAdd(&g_ticket, 1);
        __syncthreads();
        const int chunk = s_chunk;
        __syncthreads();
        if (chunk >= NCHUNKS) return;   // uniform across CTA

        const int q  = chunk * CHUNK_PX + px;      // flat pixel 0..7199
        const int n  = q / (HO*WO);
        const int r  = q - n*(HO*WO);
        const int ho = r / WO;
        const int wo = r - ho*WO;

        const float* v1p = g_v1 + (n*CIN*H + ho)*W + wo;
        const float* v2p = g_v2 + (n*CIN*H + ho)*W + wo;

        float m11[8], m12[8], m21[8], m22[8];
        #pragma unroll
        for (int k = 0; k < 8; k++) { m11[k]=0.f; m12[k]=0.f; m21[k]=0.f; m22[k]=0.f; }

        #pragma unroll 1
        for (int ij = 0; ij < 9; ij++) {
            const int i = ij / 3;
            const int j = ij - 3*i;
            const float*  a1  = v1p + i*W + j;
            const float*  a2  = v2p + i*W + j;
            const float4* w1p = reinterpret_cast<const float4*>(g_ek1) + (ij*CIN)*(COUT/4) + cg*2;
            const float4* w2p = reinterpret_cast<const float4*>(g_ek2) + (ij*CIN)*(COUT/4) + cg*2;

            #pragma unroll 4
            for (int ci = 0; ci < CIN; ci++) {
                const float  x1 = __ldg(a1 + ci*(H*W));
                const float  x2 = __ldg(a2 + ci*(H*W));
                const float4 wa = __ldg(w1p + ci*(COUT/4));
                const float4 wb = __ldg(w1p + ci*(COUT/4) + 1);
                const float4 wc = __ldg(w2p + ci*(COUT/4));
                const float4 wd = __ldg(w2p + ci*(COUT/4) + 1);
                const float w1v[8] = {wa.x, wa.y, wa.z, wa.w, wb.x, wb.y, wb.z, wb.w};
                const float w2v[8] = {wc.x, wc.y, wc.z, wc.w, wd.x, wd.y, wd.z, wd.w};
                #pragma unroll
                for (int k = 0; k < 8; k++) {
                    m11[k] = fmaxf(m11[k], x1 * w1v[k]);
                    m12[k] = fmaxf(m12[k], x1 * w2v[k]);
                    m21[k] = fmaxf(m21[k], x2 * w1v[k]);
                    m22[k] = fmaxf(m22[k], x2 * w2v[k]);
                }
            }
        }

        float res[8];
        #pragma unroll
        for (int k = 0; k < 8; k++)
            res[k] = m11[k] - m12[k] - m21[k] + m22[k] + __ldg(bias + c0 + k);

        float4* op = reinterpret_cast<float4*>(out + (size_t)q*COUT + c0);
        op[0] = make_float4(res[0], res[1], res[2], res[3]);
        op[1] = make_float4(res[4], res[5], res[6], res[7]);
    }
}

// ---------------------------------------------------------------------------
extern "C" void kernel_launch(void* const* d_in, const int* in_sizes, int n_in,
                              void* d_out, int out_size) {
    const float* x    = (const float*)d_in[0];
    const float* k1   = (const float*)d_in[1];
    const float* k2   = (const float*)d_in[2];
    const float* bias = (const float*)d_in[3];
    float* out = (float*)d_out;

    prep_vals<<<N_IMG*H, dim3(32,32)>>>(x);
    prep_w<<<(PDIM*COUT + 255)/256, 256>>>(k1, k2);
    morph_main<<<148*4, 128>>>(bias, out);
}

// round 2
// speedup vs baseline: 1.0232x; 1.0232x over previous
#include <cuda_runtime.h>

#define N_IMG 8
#define H 32
#define W 32
#define CIN 32
#define COUT 64
#define HO 30
#define WO 30
#define NPIX (N_IMG*HO*WO)       // 7200
#define CHUNK_PX 16
#define NCHUNKS (NPIX/CHUNK_PX)  // 450 (exact)
#define PDIM (3*3*CIN)           // 288

// Scratch (device globals: no allocation allowed in kernel_launch)
__device__ float2 g_v[N_IMG*CIN*H*W];   // {max(x,0.1), max(-x,0.1)}, NCHW
__device__ float  g_ek1[PDIM*COUT];     // exp(k1), [p][cout]
__device__ float  g_ek2[PDIM*COUT];     // exp(k2), [p][cout]
__device__ int    g_ticket;

// ---------------------------------------------------------------------------
// Fused prep: blocks [0,256) do clamp + NHWC->NCHW transpose (float2-packed),
// blocks [256,274) do exp(weights); one thread resets the ticket.
// ---------------------------------------------------------------------------
__global__ void prep(const float* __restrict__ x,
                     const float* __restrict__ k1,
                     const float* __restrict__ k2) {
    const int b = blockIdx.x;
    if (b < 256) {
        __shared__ float tile[32][33];
        const int n = b >> 5;
        const int h = b & 31;
        {
            const int c = threadIdx.x;   // contiguous in gmem -> coalesced read
            const int w = threadIdx.y;
            tile[w][c] = x[(((n*H + h)*W + w)*CIN) + c];
        }
        __syncthreads();
        {
            const int w = threadIdx.x;   // contiguous in output -> coalesced write
            const int c = threadIdx.y;
            const float v = tile[w][c];
            const int o = ((n*CIN + c)*H + h)*W + w;
            g_v[o] = make_float2(fmaxf(v, 0.1f), fmaxf(-v, 0.1f));
        }
    } else {
        const int i = (b - 256)*1024 + threadIdx.y*32 + threadIdx.x;
        if (i == 0) g_ticket = 0;
        if (i < PDIM*COUT) {
            g_ek1[i] = expf(k1[i]);
            g_ek2[i] = expf(k2[i]);
        }
    }
}

// ---------------------------------------------------------------------------
// Main: dynamic-ticket chunks of 16 pixels x 64 couts.
// 256 threads = 16 cout-groups (4 couts each, lanes 0..15) x 16 pixel slots.
//   cg = t & 15  -> output stores coalesced (full 64-cout row contiguous)
//   px = t >> 4  -> v loads are 2-address warp broadcasts
// Per ci: 1 LDG.64 (v pair) + 2 LDG.128 (w) + 16 FMUL + 16 FMNMX.
// ---------------------------------------------------------------------------
__global__ void __launch_bounds__(256, 3)
morph_main(const float* __restrict__ bias, float* __restrict__ out) {
    __shared__ int s_chunk;
    const int t  = threadIdx.x;
    const int cg = t & 15;        // cout group 0..15 (4 couts each)
    const int px = t >> 4;        // pixel slot within chunk
    const int c0 = cg * 4;

    // Hoisted invariants
    const float4 bv = *reinterpret_cast<const float4*>(bias + c0);
    const float4* __restrict__ w1base = reinterpret_cast<const float4*>(g_ek1) + cg;
    const float4* __restrict__ w2base = reinterpret_cast<const float4*>(g_ek2) + cg;

    for (;;) {
        if (t == 0) s_chunk = atomicAdd(&g_ticket, 1);
        __syncthreads();
        const int chunk = s_chunk;
        __syncthreads();
        if (chunk >= NCHUNKS) return;   // uniform across CTA

        const int q  = chunk * CHUNK_PX + px;      // flat pixel 0..7199
        const int n  = q / (HO*WO);
        const int r  = q - n*(HO*WO);
        const int ho = r / WO;
        const int wo = r - ho*WO;

        const float2* __restrict__ vbase = g_v + (n*CIN*H + ho)*W + wo;

        float m11[4], m12[4], m21[4], m22[4];
        #pragma unroll
        for (int k = 0; k < 4; k++) { m11[k]=0.f; m12[k]=0.f; m21[k]=0.f; m22[k]=0.f; }

        #pragma unroll 1
        for (int ij = 0; ij < 9; ij++) {
            const int i = ij / 3;
            const int j = ij - 3*i;
            const float2* __restrict__ vp  = vbase + i*W + j;
            const float4* __restrict__ w1p = w1base + (ij*CIN)*(COUT/4);
            const float4* __restrict__ w2p = w2base + (ij*CIN)*(COUT/4);

            #pragma unroll 8
            for (int ci = 0; ci < CIN; ci++) {
                const float2 v  = __ldg(vp + ci*(H*W));
                const float4 w1 = __ldg(w1p + ci*(COUT/4));
                const float4 w2 = __ldg(w2p + ci*(COUT/4));
                m11[0] = fmaxf(m11[0], v.x * w1.x);
                m11[1] = fmaxf(m11[1], v.x * w1.y);
                m11[2] = fmaxf(m11[2], v.x * w1.z);
                m11[3] = fmaxf(m11[3], v.x * w1.w);
                m12[0] = fmaxf(m12[0], v.x * w2.x);
                m12[1] = fmaxf(m12[1], v.x * w2.y);
                m12[2] = fmaxf(m12[2], v.x * w2.z);
                m12[3] = fmaxf(m12[3], v.x * w2.w);
                m21[0] = fmaxf(m21[0], v.y * w1.x);
                m21[1] = fmaxf(m21[1], v.y * w1.y);
                m21[2] = fmaxf(m21[2], v.y * w1.z);
                m21[3] = fmaxf(m21[3], v.y * w1.w);
                m22[0] = fmaxf(m22[0], v.y * w2.x);
                m22[1] = fmaxf(m22[1], v.y * w2.y);
                m22[2] = fmaxf(m22[2], v.y * w2.z);
                m22[3] = fmaxf(m22[3], v.y * w2.w);
            }
        }

        float4 res;
        res.x = m11[0] - m12[0] - m21[0] + m22[0] + bv.x;
        res.y = m11[1] - m12[1] - m21[1] + m22[1] + bv.y;
        res.z = m11[2] - m12[2] - m21[2] + m22[2] + bv.z;
        res.w = m11[3] - m12[3] - m21[3] + m22[3] + bv.w;

        *reinterpret_cast<float4*>(out + (size_t)q*COUT + c0) = res;
    }
}

// ---------------------------------------------------------------------------
extern "C" void kernel_launch(void* const* d_in, const int* in_sizes, int n_in,
                              void* d_out, int out_size) {
    const float* x    = (const float*)d_in[0];
    const float* k1   = (const float*)d_in[1];
    const float* k2   = (const float*)d_in[2];
    const float* bias = (const float*)d_in[3];
    float* out = (float*)d_out;

    prep<<<256 + (PDIM*COUT + 1023)/1024, dim3(32,32)>>>(x, k1, k2);
    morph_main<<<148*3, 256>>>(bias, out);
}

// round 4
// speedup vs baseline: 1.1884x; 1.1615x over previous
#include <cuda_runtime.h>

#define N_IMG 8
#define H 32
#define W 32
#define CIN 32
#define COUT 64
#define HO 30
#define WO 30
#define NPIX (N_IMG*HO*WO)       // 7200
#define PDIM (3*3*CIN)           // 288

// Scratch (device globals: no allocation allowed in kernel_launch)
__device__ __align__(16) float2 g_v[N_IMG*H*W*CIN];   // NHWC: {max(x,0.1), max(-x,0.1)}
__device__ __align__(16) float  g_ek1[PDIM*COUT];     // exp(k1), [p][cout]
__device__ __align__(16) float  g_ek2[PDIM*COUT];     // exp(k2), [p][cout]

#define NV4 (N_IMG*H*W*CIN/4)    // 65536 float4 elements of x
#define VBLOCKS (NV4/256)        // 256
#define WBLOCKS ((PDIM*COUT + 255)/256)  // 72

// ---------------------------------------------------------------------------
// Fused prep (pure streaming, no transpose):
//   blocks [0,VBLOCKS):  v = {max(x,0.1), max(-x,0.1)} elementwise, float4 I/O
//   blocks [VBLOCKS, VBLOCKS+WBLOCKS): exp(weights)
// ---------------------------------------------------------------------------
__global__ void prep(const float* __restrict__ x,
                     const float* __restrict__ k1,
                     const float* __restrict__ k2) {
    const int b = blockIdx.x;
    if (b < VBLOCKS) {
        const int e4 = b*256 + threadIdx.x;          // float4 index, 65536 total
        const float4 xv = reinterpret_cast<const float4*>(x)[e4];
        float4 lo, hi;
        lo.x = fmaxf(xv.x, 0.1f);  lo.y = fmaxf(-xv.x, 0.1f);
        lo.z = fmaxf(xv.y, 0.1f);  lo.w = fmaxf(-xv.y, 0.1f);
        hi.x = fmaxf(xv.z, 0.1f);  hi.y = fmaxf(-xv.z, 0.1f);
        hi.z = fmaxf(xv.w, 0.1f);  hi.w = fmaxf(-xv.w, 0.1f);
        float4* vp = reinterpret_cast<float4*>(g_v) + e4*2;
        vp[0] = lo;
        vp[1] = hi;
    } else {
        const int i = (b - VBLOCKS)*256 + threadIdx.x;
        if (i < PDIM*COUT) {
            g_ek1[i] = expf(k1[i]);
            g_ek2[i] = expf(k2[i]);
        }
    }
}

// ---------------------------------------------------------------------------
// Main: one WARP per 2 pixels x 64 couts.
//   lane = cg(0..15, 4 couts each) + 16*ps(pixel 0/1)
//   grid = 3600 single-warp CTAs -> 24-25 CTAs/SM, ~4% tail slack
// Per inner iter: 1 LDG.64 (v pair, broadcast) + 2 LDG.128 (w, coalesced across
// lanes, L1-resident) + 16 FMUL + 16 FMNMX.
// No smem, no syncthreads, no atomics.
// ---------------------------------------------------------------------------
__global__ void __launch_bounds__(32)
morph_main(const float* __restrict__ bias, float* __restrict__ out) {
    const int t  = threadIdx.x;
    const int cg = t & 15;        // cout group 0..15 (4 couts)
    const int ps = t >> 4;        // pixel slot 0/1
    const int c0 = cg * 4;

    const int q  = blockIdx.x*2 + ps;   // flat pixel 0..7199
    const int n  = q / (HO*WO);
    const int r  = q - n*(HO*WO);
    const int ho = r / WO;
    const int wo = r - ho*WO;

    // NHWC: v for (ho+i, wo+j, ci) = vbase[(i*W + j)*CIN + ci]
    const float2* __restrict__ vbase = g_v + ((n*H + ho)*W + wo)*CIN;
    const float4* __restrict__ w1p = reinterpret_cast<const float4*>(g_ek1) + cg;
    const float4* __restrict__ w2p = reinterpret_cast<const float4*>(g_ek2) + cg;

    float m11[4], m12[4], m21[4], m22[4];
    #pragma unroll
    for (int k = 0; k < 4; k++) { m11[k]=0.f; m12[k]=0.f; m21[k]=0.f; m22[k]=0.f; }

    // Patch dim p = i*96 + (j*CIN + ci); for fixed i, (j,ci) is 96 CONTIGUOUS
    // float2's in v and 96 contiguous float4 rows in the weight tables.
    #pragma unroll 1
    for (int i = 0; i < 3; i++) {
        const float2* __restrict__ vp  = vbase + i*(W*CIN);
        const float4* __restrict__ a1  = w1p + (i*96)*(COUT/4);
        const float4* __restrict__ a2  = w2p + (i*96)*(COUT/4);

        #pragma unroll 8
        for (int k = 0; k < 96; k++) {
            const float2 v  = __ldg(vp + k);
            const float4 w1 = __ldg(a1 + k*(COUT/4));
            const float4 w2 = __ldg(a2 + k*(COUT/4));
            m11[0] = fmaxf(m11[0], v.x * w1.x);
            m11[1] = fmaxf(m11[1], v.x * w1.y);
            m11[2] = fmaxf(m11[2], v.x * w1.z);
            m11[3] = fmaxf(m11[3], v.x * w1.w);
            m12[0] = fmaxf(m12[0], v.x * w2.x);
            m12[1] = fmaxf(m12[1], v.x * w2.y);
            m12[2] = fmaxf(m12[2], v.x * w2.z);
            m12[3] = fmaxf(m12[3], v.x * w2.w);
            m21[0] = fmaxf(m21[0], v.y * w1.x);
            m21[1] = fmaxf(m21[1], v.y * w1.y);
            m21[2] = fmaxf(m21[2], v.y * w1.z);
            m21[3] = fmaxf(m21[3], v.y * w1.w);
            m22[0] = fmaxf(m22[0], v.y * w2.x);
            m22[1] = fmaxf(m22[1], v.y * w2.y);
            m22[2] = fmaxf(m22[2], v.y * w2.z);
            m22[3] = fmaxf(m22[3], v.y * w2.w);
        }
    }

    const float4 bv = *reinterpret_cast<const float4*>(bias + c0);
    float4 res;
    res.x = m11[0] - m12[0] - m21[0] + m22[0] + bv.x;
    res.y = m11[1] - m12[1] - m21[1] + m22[1] + bv.y;
    res.z = m11[2] - m12[2] - m21[2] + m22[2] + bv.z;
    res.w = m11[3] - m12[3] - m21[3] + m22[3] + bv.w;

    *reinterpret_cast<float4*>(out + (size_t)q*COUT + c0) = res;
}

// ---------------------------------------------------------------------------
extern "C" void kernel_launch(void* const* d_in, const int* in_sizes, int n_in,
                              void* d_out, int out_size) {
    const float* x    = (const float*)d_in[0];
    const float* k1   = (const float*)d_in[1];
    const float* k2   = (const float*)d_in[2];
    const float* bias = (const float*)d_in[3];
    float* out = (float*)d_out;

    prep<<<VBLOCKS + WBLOCKS, 256>>>(x, k1, k2);
    morph_main<<<NPIX/2, 32>>>(bias, out);
}

// round 6
// speedup vs baseline: 1.2095x; 1.0177x over previous
#include <cuda_runtime.h>

#define N_IMG 8
#define H 32
#define W 32
#define CIN 32
#define COUT 64
#define HO 30
#define WO 30
#define NPIX (N_IMG*HO*WO)       // 7200
#define PDIM (3*3*CIN)           // 288

typedef unsigned long long u64;

// Scratch (device globals: no allocation allowed in kernel_launch)
__device__ __align__(16) float2 g_v[N_IMG*H*W*CIN];   // NHWC: {max(x,0.1), max(-x,0.1)}
__device__ __align__(16) float  g_ek1[PDIM*COUT];     // exp(k1), [p][cout]
__device__ __align__(16) float  g_ek2[PDIM*COUT];     // exp(k2), [p][cout]

#define NV4 (N_IMG*H*W*CIN/4)    // 65536 float4 elements of x
#define VBLOCKS (NV4/256)        // 256
#define WBLOCKS ((PDIM*COUT + 255)/256)  // 72

// ---- packed f32x2 helpers ---------------------------------------------
__device__ __forceinline__ u64 pack2(float lo, float hi) {
    u64 d; asm("mov.b64 %0, {%1, %2};" : "=l"(d) : "f"(lo), "f"(hi)); return d;
}
// packed multiply (FFMA2 path), then scalar max into two accumulators.
// The mov.b64 unpack is register-pair aliasing; ptxas elides it.
__device__ __forceinline__ void mulmax(u64 v, u64 w, float& a0, float& a1) {
    float lo, hi;
    asm("{\n\t"
        ".reg .b64 t;\n\t"
        "mul.rn.f32x2 t, %2, %3;\n\t"
        "mov.b64 {%0, %1}, t;\n\t"
        "}" : "=f"(lo), "=f"(hi) : "l"(v), "l"(w));
    a0 = fmaxf(a0, lo);
    a1 = fmaxf(a1, hi);
}

// ---------------------------------------------------------------------------
// Fused prep (pure streaming):
//   blocks [0,VBLOCKS):  v = {max(x,0.1), max(-x,0.1)} elementwise, float4 I/O
//   blocks [VBLOCKS, VBLOCKS+WBLOCKS): exp(weights)
// ---------------------------------------------------------------------------
__global__ void prep(const float* __restrict__ x,
                     const float* __restrict__ k1,
                     const float* __restrict__ k2) {
    const int b = blockIdx.x;
    if (b < VBLOCKS) {
        const int e4 = b*256 + threadIdx.x;          // float4 index, 65536 total
        const float4 xv = reinterpret_cast<const float4*>(x)[e4];
        float4 lo, hi;
        lo.x = fmaxf(xv.x, 0.1f);  lo.y = fmaxf(-xv.x, 0.1f);
        lo.z = fmaxf(xv.y, 0.1f);  lo.w = fmaxf(-xv.y, 0.1f);
        hi.x = fmaxf(xv.z, 0.1f);  hi.y = fmaxf(-xv.z, 0.1f);
        hi.z = fmaxf(xv.w, 0.1f);  hi.w = fmaxf(-xv.w, 0.1f);
        float4* vp = reinterpret_cast<float4*>(g_v) + e4*2;
        vp[0] = lo;
        vp[1] = hi;
    } else {
        const int i = (b - VBLOCKS)*256 + threadIdx.x;
        if (i < PDIM*COUT) {
            g_ek1[i] = expf(k1[i]);
            g_ek2[i] = expf(k2[i]);
        }
    }
}

// ---------------------------------------------------------------------------
// Main: CTA = 64 threads = 2 warps, covering 2 pixels x 64 couts.
//   lane: cg = l&15 (4 couts each), ps = l>>4 (pixel 0/1)
//   warp w handles k in [48w, 48w+48) of each kernel row (p-split).
// Per inner iter per thread: 1 LDG.64 (v, broadcast) + 2 LDG.128 (w pairs)
//   + 2 packs + 8 MUL.f32x2 + 16 FMNMX.
// Warp 1 publishes partial maxes to smem; warp 0 combines + stores.
// ---------------------------------------------------------------------------
__global__ void __launch_bounds__(64, 14)
morph_main(const float* __restrict__ bias, float* __restrict__ out) {
    __shared__ float4 s_red[32][4];

    const int t    = threadIdx.x;
    const int lane = t & 31;
    const int wrp  = t >> 5;      // 0 or 1: k-half
    const int cg   = lane & 15;   // cout group (4 couts)
    const int ps   = lane >> 4;   // pixel slot 0/1
    const int c0   = cg * 4;

    const int q  = blockIdx.x*2 + ps;   // flat pixel 0..7199
    const int n  = q / (HO*WO);
    const int r  = q - n*(HO*WO);
    const int ho = r / WO;
    const int wo = r - ho*WO;

    // NHWC: v for (ho+i, wo+j, ci) = vbase[(i*W + j)*CIN + ci], (j,ci) contiguous
    const float2* __restrict__ vbase = g_v + ((n*H + ho)*W + wo)*CIN;
    // weight row = 64 floats = 16 ulonglong2 (two f32x2 each); element cg
    const ulonglong2* __restrict__ w1p = reinterpret_cast<const ulonglong2*>(g_ek1) + cg;
    const ulonglong2* __restrict__ w2p = reinterpret_cast<const ulonglong2*>(g_ek2) + cg;

    const int klo = wrp * 48;

    float m11[4], m12[4], m21[4], m22[4];
    #pragma unroll
    for (int k = 0; k < 4; k++) { m11[k]=0.f; m12[k]=0.f; m21[k]=0.f; m22[k]=0.f; }

    #pragma unroll 1
    for (int i = 0; i < 3; i++) {
        const float2*     __restrict__ vp = vbase + i*(W*CIN) + klo;
        const ulonglong2* __restrict__ a1 = w1p + (i*96 + klo)*16;
        const ulonglong2* __restrict__ a2 = w2p + (i*96 + klo)*16;

        #pragma unroll 8
        for (int k = 0; k < 48; k++) {
            const float2     v  = __ldg(vp + k);
            const ulonglong2 w1 = __ldg(a1 + k*16);
            const ulonglong2 w2 = __ldg(a2 + k*16);
            const u64 vxx = pack2(v.x, v.x);
            const u64 vyy = pack2(v.y, v.y);
            mulmax(vxx, w1.x, m11[0], m11[1]);
            mulmax(vxx, w1.y, m11[2], m11[3]);
            mulmax(vxx, w2.x, m12[0], m12[1]);
            mulmax(vxx, w2.y, m12[2], m12[3]);
            mulmax(vyy, w1.x, m21[0], m21[1]);
            mulmax(vyy, w1.y, m21[2], m21[3]);
            mulmax(vyy, w2.x, m22[0], m22[1]);
            mulmax(vyy, w2.y, m22[2], m22[3]);
        }
    }

    // Partial difference to shrink smem traffic: d1 = m11-m12, d2 = m22-m21
    float4 d1, d2;
    d1.x = m11[0]-m12[0]; d1.y = m11[1]-m12[1]; d1.z = m11[2]-m12[2]; d1.w = m11[3]-m12[3];
    d2.x = m22[0]-m21[0]; d2.y = m22[1]-m21[1]; d2.z = m22[2]-m21[2]; d2.w = m22[3]-m21[3];
    // NOTE: max must be combined BEFORE differencing, so publish raw maxes.
    // (d1/d2 only valid if warp-local; recompute after combine instead.)

    if (wrp == 1) {
        s_red[lane][0] = make_float4(m11[0], m11[1], m11[2], m11[3]);
        s_red[lane][1] = make_float4(m12[0], m12[1], m12[2], m12[3]);
        s_red[lane][2] = make_float4(m21[0], m21[1], m21[2], m21[3]);
        s_red[lane][3] = make_float4(m22[0], m22[1], m22[2], m22[3]);
    }
    __syncthreads();
    if (wrp == 0) {
        const float4 o11 = s_red[lane][0];
        const float4 o12 = s_red[lane][1];
        const float4 o21 = s_red[lane][2];
        const float4 o22 = s_red[lane][3];
        m11[0] = fmaxf(m11[0], o11.x); m11[1] = fmaxf(m11[1], o11.y);
        m11[2] = fmaxf(m11[2], o11.z); m11[3] = fmaxf(m11[3], o11.w);
        m12[0] = fmaxf(m12[0], o12.x); m12[1] = fmaxf(m12[1], o12.y);
        m12[2] = fmaxf(m12[2], o12.z); m12[3] = fmaxf(m12[3], o12.w);
        m21[0] = fmaxf(m21[0], o21.x); m21[1] = fmaxf(m21[1], o21.y);
        m21[2] = fmaxf(m21[2], o21.z); m21[3] = fmaxf(m21[3], o21.w);
        m22[0] = fmaxf(m22[0], o22.x); m22[1] = fmaxf(m22[1], o22.y);
        m22[2] = fmaxf(m22[2], o22.z); m22[3] = fmaxf(m22[3], o22.w);

        const float4 bv = *reinterpret_cast<const float4*>(bias + c0);
        float4 res;
        res.x = m11[0] - m12[0] - m21[0] + m22[0] + bv.x;
        res.y = m11[1] - m12[1] - m21[1] + m22[1] + bv.y;
        res.z = m11[2] - m12[2] - m21[2] + m22[2] + bv.z;
        res.w = m11[3] - m12[3] - m21[3] + m22[3] + bv.w;

        *reinterpret_cast<float4*>(out + (size_t)q*COUT + c0) = res;
    }
}

// ---------------------------------------------------------------------------
extern "C" void kernel_launch(void* const* d_in, const int* in_sizes, int n_in,
                              void* d_out, int out_size) {
    const float* x    = (const float*)d_in[0];
    const float* k1   = (const float*)d_in[1];
    const float* k2   = (const float*)d_in[2];
    const float* bias = (const float*)d_in[3];
    float* out = (float*)d_out;

    prep<<<VBLOCKS + WBLOCKS, 256>>>(x, k1, k2);
    morph_main<<<NPIX/2, 64>>>(bias, out);
}